// round 6
// baseline (speedup 1.0000x reference)
#include <cuda_runtime.h>
#include <math.h>

#define NN 100000
#define NE 1600000
#define SCAN_G 196   // ceil(100000/512)

// ---------------- scratch (__device__ globals; no allocation) ----------------
__device__ __align__(16) int   g_rowptr[NN + 1];
__device__ __align__(16) int   g_cursor[NN];
__device__ __align__(16) int   g_csr[NE];
__device__ __align__(16) float g_y[NN * 64];      // x @ W1l
__device__ __align__(16) float g_z[NN * 64];      // x @ W1r + b1
__device__ __align__(16) float g_pq[NN * 32];     // per node: [p2(16) | q2(16)]
__device__ unsigned long long  g_state[SCAN_G];
__device__ int                 g_ticket;

// ---------------- packed f32x2 helpers ----------------
__device__ __forceinline__ unsigned long long bcast2(float a) {
    unsigned long long r;
    asm("mov.b64 %0,{%1,%1};" : "=l"(r) : "f"(a));
    return r;
}
__device__ __forceinline__ float2 unpk2(unsigned long long v) {
    float2 r;
    asm("mov.b64 {%0,%1},%2;" : "=f"(r.x), "=f"(r.y) : "l"(v));
    return r;
}
#define FMA2(d, a, b, c) asm("fma.rn.f32x2 %0,%1,%2,%3;" : "=l"(d) : "l"(a), "l"(b), "l"(c))
#define ADD2(d, a, b)    asm("add.rn.f32x2 %0,%1,%2;"    : "=l"(d) : "l"(a), "l"(b))
#define MUL2(d, a, b)    asm("mul.rn.f32x2 %0,%1,%2;"    : "=l"(d) : "l"(a), "l"(b))

// ---------------------------------------------------------------------------
// CSR build
// ---------------------------------------------------------------------------
__global__ void k_hist(const int* __restrict__ ei) {
    int e = blockIdx.x * blockDim.x + threadIdx.x;
    if (e < NE) atomicAdd(&g_cursor[__ldg(ei + NE + e)], 1);
}

__device__ __forceinline__ int warp_incl_scan(int v) {
    int lane = threadIdx.x & 31;
#pragma unroll
    for (int d = 1; d < 32; d <<= 1) {
        int t = __shfl_up_sync(0xFFFFFFFFu, v, d);
        if (lane >= d) v += t;
    }
    return v;
}

__global__ void __launch_bounds__(512) k_scan() {
    __shared__ int ws[16];
    __shared__ int sbid;
    __shared__ int s_prefix;
    int tid = threadIdx.x;
    if (tid == 0) { sbid = atomicAdd(&g_ticket, 1); s_prefix = 0; }
    __syncthreads();
    int bid = sbid;
    int g = bid * 512 + tid;
    int v = (g < NN) ? g_cursor[g] : 0;
    int inc = warp_incl_scan(v);
    int wid = tid >> 5, lane = tid & 31;
    if (lane == 31) ws[wid] = inc;
    __syncthreads();
    if (wid == 0) {
        int t = (lane < 16) ? ws[lane] : 0;
        t = warp_incl_scan(t);
        if (lane < 16) ws[lane] = t;
    }
    __syncthreads();
    int off = (wid > 0) ? ws[wid - 1] : 0;
    int linc = inc + off;

    if (tid == 511) {
        unsigned long long pk = ((unsigned long long)linc << 2) | (bid == 0 ? 2ull : 1ull);
        __threadfence();
        atomicExch(&g_state[bid], pk);
    }
    if (bid > 0 && tid == 0) {
        long long run = 0;
        int p = bid - 1;
        while (true) {
            unsigned long long st;
            do { st = *((volatile unsigned long long*)&g_state[p]); } while ((st & 3ull) == 0);
            run += (long long)(st >> 2);
            if ((st & 3ull) == 2ull) break;
            p--;
        }
        s_prefix = (int)run;
    }
    __syncthreads();
    int pref = s_prefix;
    if (bid > 0 && tid == 511) {
        unsigned long long pk = ((unsigned long long)(pref + linc) << 2) | 2ull;
        __threadfence();
        atomicExch(&g_state[bid], pk);
    }
    int excl = pref + (linc - v);
    if (g < NN) { g_rowptr[g] = excl; g_cursor[g] = excl; }
    if (g == NN) g_rowptr[NN] = excl;
}

__global__ void k_fill(const int* __restrict__ ei) {
    int e = blockIdx.x * blockDim.x + threadIdx.x;
    if (e < NE) {
        int src = __ldg(ei + e);
        int dst = __ldg(ei + NE + e);
        int pos = atomicAdd(&g_cursor[dst], 1);
        g_csr[pos] = src;
    }
}

// ---------------------------------------------------------------------------
// Precompute: y = x@W1l, z = x@W1r + b1.
// 256 threads, 128 nodes/block; thread pairs: even -> y, odd -> z.
// Weights warp-uniform-per-half from smem (2-way broadcast), x staged in
// [k][node] tiles so the feature read is a broadcast too.
// ---------------------------------------------------------------------------
#define PC_TS 130
#define PC_SMEM (8192 + 16 * PC_TS + 64)

__global__ void __launch_bounds__(256) precompute_kernel(
    const float* __restrict__ x,
    const float* __restrict__ W1l, const float* __restrict__ W1r,
    const float* __restrict__ b1)
{
    extern __shared__ float smem[];
    float* sW  = smem;              // [0..4095]=W1l, [4096..8191]=W1r  (k*64+j)
    float* sXt = sW + 8192;         // [k*PC_TS + node_local], 16 k rows
    float* sB1 = sXt + 16 * PC_TS;  // 64

    int tid = threadIdx.x;
    for (int i = tid; i < 1024; i += 256) {
        ((float4*)sW)[i]          = ((const float4*)W1l)[i];
        ((float4*)(sW + 4096))[i] = ((const float4*)W1r)[i];
    }
    if (tid < 64) sB1[tid] = b1[tid];

    int nbase = blockIdx.x * 128;
    int nl = tid >> 1;
    int node = nbase + nl;
    int m = tid & 1;                         // 0: W1l->y, 1: W1r->z
    const float* Wsel = sW + m * 4096;

    unsigned long long acc[32];
#pragma unroll
    for (int j = 0; j < 32; j++) acc[j] = 0ull;

    const float4* x4 = (const float4*)x;
    float4 z4 = make_float4(0.f, 0.f, 0.f, 0.f);

    for (int kb = 0; kb < 4; kb++) {
        __syncthreads();
        for (int i = tid; i < 512; i += 256) {
            int nn = i >> 2, cc = i & 3;
            int gn = nbase + nn;
            float4 v = (gn < NN) ? __ldg(x4 + (size_t)gn * 16 + kb * 4 + cc) : z4;
            int kr = cc * 4;
            sXt[(kr + 0) * PC_TS + nn] = v.x;
            sXt[(kr + 1) * PC_TS + nn] = v.y;
            sXt[(kr + 2) * PC_TS + nn] = v.z;
            sXt[(kr + 3) * PC_TS + nn] = v.w;
        }
        __syncthreads();
#pragma unroll
        for (int k = 0; k < 16; k++) {
            int kg = kb * 16 + k;
            unsigned long long X = bcast2(sXt[k * PC_TS + nl]);
            const ulonglong2* w = (const ulonglong2*)(Wsel + kg * 64);
#pragma unroll
            for (int jh = 0; jh < 16; jh++) {
                ulonglong2 ww = w[jh];
                FMA2(acc[2 * jh],     X, ww.x, acc[2 * jh]);
                FMA2(acc[2 * jh + 1], X, ww.y, acc[2 * jh + 1]);
            }
        }
    }

    if (node < NN) {
        float o[64];
#pragma unroll
        for (int p = 0; p < 32; p++) {
            float2 u = unpk2(acc[p]);
            o[2 * p]     = u.x;
            o[2 * p + 1] = u.y;
        }
        if (m) {
#pragma unroll
            for (int j = 0; j < 64; j++) o[j] += sB1[j];
        }
        float* base = (m ? g_z : g_y) + (size_t)node * 64;
#pragma unroll
        for (int q = 0; q < 16; q++) ((float4*)base)[q] = *(float4*)(o + 4 * q);
    }
}

// ---------------------------------------------------------------------------
// Gather + layer1 + proj: h1 = relu(mean(y) + z); [p2|q2] = h1@[W2l|W2r]+[0|b2]
// 256 threads, 16 nodes/block; 16 lanes/node for the gather (LDG.128/lane).
// ---------------------------------------------------------------------------
#define GH_TS 66
#define GH_SMEM (2048 + 16 * GH_TS + 32)

__global__ void __launch_bounds__(256) gather_l1_proj_kernel(
    const float* __restrict__ W2l, const float* __restrict__ W2r,
    const float* __restrict__ b2)
{
    extern __shared__ float smem[];
    float* sW2 = smem;             // [k*32 + j]: j<16 W2l, else W2r
    float* sH  = sW2 + 2048;       // [node_local*GH_TS + k]
    float* sB2 = sH + 16 * GH_TS;  // 32

    int tid = threadIdx.x;
    for (int i = tid; i < 64 * 16; i += 256) {
        int k = i >> 4, j = i & 15;
        sW2[k * 32 + j]      = W2l[i];
        sW2[k * 32 + 16 + j] = W2r[i];
    }
    if (tid < 16) { sB2[tid] = 0.f; sB2[16 + tid] = b2[tid]; }

    int nl = tid >> 4;
    int c  = tid & 15;
    int node = blockIdx.x * 16 + nl;
    bool nv = node < NN;

    // gather mean of y
    int s = 0, e = 0;
    if (nv) { s = __ldg(g_rowptr + node); e = __ldg(g_rowptr + node + 1); }
    unsigned long long a0 = 0ull, a1 = 0ull;
    const ulonglong2* y2 = (const ulonglong2*)g_y;
    int i = s;
    for (; i + 4 <= e; i += 4) {
        int s0 = __ldg(g_csr + i);
        int s1 = __ldg(g_csr + i + 1);
        int s2 = __ldg(g_csr + i + 2);
        int s3 = __ldg(g_csr + i + 3);
        ulonglong2 v0 = __ldg(y2 + (size_t)s0 * 16 + c);
        ulonglong2 v1 = __ldg(y2 + (size_t)s1 * 16 + c);
        ulonglong2 v2 = __ldg(y2 + (size_t)s2 * 16 + c);
        ulonglong2 v3 = __ldg(y2 + (size_t)s3 * 16 + c);
        ADD2(a0, a0, v0.x); ADD2(a1, a1, v0.y);
        ADD2(a0, a0, v1.x); ADD2(a1, a1, v1.y);
        ADD2(a0, a0, v2.x); ADD2(a1, a1, v2.y);
        ADD2(a0, a0, v3.x); ADD2(a1, a1, v3.y);
    }
    for (; i < e; i++) {
        int s0 = __ldg(g_csr + i);
        ulonglong2 v0 = __ldg(y2 + (size_t)s0 * 16 + c);
        ADD2(a0, a0, v0.x); ADD2(a1, a1, v0.y);
    }
    unsigned long long I = bcast2(1.f / fmaxf((float)(e - s), 1.f));
    MUL2(a0, a0, I);
    MUL2(a1, a1, I);

    ulonglong2 zz = make_ulonglong2(0ull, 0ull);
    if (nv) zz = __ldg((const ulonglong2*)g_z + (size_t)node * 16 + c);
    float2 m0 = unpk2(a0), m1 = unpk2(a1);
    float2 z0 = unpk2(zz.x), z1 = unpk2(zz.y);
    float* hrow = sH + nl * GH_TS + c * 4;
    hrow[0] = fmaxf(m0.x + z0.x, 0.f);
    hrow[1] = fmaxf(m0.y + z0.y, 0.f);
    hrow[2] = fmaxf(m1.x + z1.x, 0.f);
    hrow[3] = fmaxf(m1.y + z1.y, 0.f);
    __syncthreads();

    // proj: thread handles 2 cols (cp, cp+1) of 32 for its node
    int cp = c * 2;
    unsigned long long acc = 0ull;
    const float* hb = sH + nl * GH_TS;
#pragma unroll
    for (int k = 0; k < 64; k++) {
        unsigned long long H = bcast2(hb[k]);
        unsigned long long w = *(const unsigned long long*)(sW2 + k * 32 + cp);
        FMA2(acc, H, w, acc);
    }
    if (nv) {
        float2 u = unpk2(acc);
        float2 o;
        o.x = u.x + sB2[cp];
        o.y = u.y + sB2[cp + 1];
        *(float2*)(g_pq + (size_t)node * 32 + cp) = o;
    }
}

// ---------------------------------------------------------------------------
// Final: gather mean(p2) + q2 -> log_softmax -> out. 4 lanes/node, unroll x4.
// ---------------------------------------------------------------------------
__global__ void __launch_bounds__(256) final_kernel(float* __restrict__ out) {
    int tid = threadIdx.x;
    int node = blockIdx.x * 64 + (tid >> 2);
    int c = tid & 3;
    bool nv = node < NN;
    int s = 0, e = 0;
    if (nv) { s = __ldg(g_rowptr + node); e = __ldg(g_rowptr + node + 1); }
    unsigned long long a0 = 0ull, a1 = 0ull;
    const ulonglong2* pq2 = (const ulonglong2*)g_pq;
    int i = s;
    for (; i + 4 <= e; i += 4) {
        int s0 = __ldg(g_csr + i);
        int s1 = __ldg(g_csr + i + 1);
        int s2 = __ldg(g_csr + i + 2);
        int s3 = __ldg(g_csr + i + 3);
        ulonglong2 v0 = __ldg(pq2 + (size_t)s0 * 8 + c);
        ulonglong2 v1 = __ldg(pq2 + (size_t)s1 * 8 + c);
        ulonglong2 v2 = __ldg(pq2 + (size_t)s2 * 8 + c);
        ulonglong2 v3 = __ldg(pq2 + (size_t)s3 * 8 + c);
        ADD2(a0, a0, v0.x); ADD2(a1, a1, v0.y);
        ADD2(a0, a0, v1.x); ADD2(a1, a1, v1.y);
        ADD2(a0, a0, v2.x); ADD2(a1, a1, v2.y);
        ADD2(a0, a0, v3.x); ADD2(a1, a1, v3.y);
    }
    for (; i < e; i++) {
        int s0 = __ldg(g_csr + i);
        ulonglong2 v0 = __ldg(pq2 + (size_t)s0 * 8 + c);
        ADD2(a0, a0, v0.x); ADD2(a1, a1, v0.y);
    }
    float invd = 1.f / fmaxf((float)(e - s), 1.f);
    float2 u0 = unpk2(a0), u1 = unpk2(a1);
    float4 q = nv ? __ldg((const float4*)g_pq + (size_t)node * 8 + 4 + c)
                  : make_float4(0.f, 0.f, 0.f, 0.f);
    float v[4];
    v[0] = u0.x * invd + q.x;
    v[1] = u0.y * invd + q.y;
    v[2] = u1.x * invd + q.z;
    v[3] = u1.y * invd + q.w;

    float m = fmaxf(fmaxf(v[0], v[1]), fmaxf(v[2], v[3]));
    m = fmaxf(m, __shfl_xor_sync(0xFFFFFFFFu, m, 1));
    m = fmaxf(m, __shfl_xor_sync(0xFFFFFFFFu, m, 2));
    float sum = expf(v[0] - m) + expf(v[1] - m) + expf(v[2] - m) + expf(v[3] - m);
    sum += __shfl_xor_sync(0xFFFFFFFFu, sum, 1);
    sum += __shfl_xor_sync(0xFFFFFFFFu, sum, 2);
    float lse = m + logf(sum);

    if (nv) {
        float4 o;
        o.x = v[0] - lse; o.y = v[1] - lse; o.z = v[2] - lse; o.w = v[3] - lse;
        ((float4*)out)[(size_t)node * 4 + c] = o;
    }
}

// ---------------------------------------------------------------------------
extern "C" void kernel_launch(void* const* d_in, const int* in_sizes, int n_in,
                              void* d_out, int out_size) {
    const float* x   = (const float*)d_in[0];
    const int*   ei  = (const int*)d_in[1];
    const float* W1l = (const float*)d_in[2];
    const float* W1r = (const float*)d_in[3];
    const float* b1  = (const float*)d_in[4];
    const float* W2l = (const float*)d_in[5];
    const float* W2r = (const float*)d_in[6];
    const float* b2  = (const float*)d_in[7];
    float* out = (float*)d_out;

    void *p_cursor, *p_state, *p_ticket;
    cudaGetSymbolAddress(&p_cursor, g_cursor);
    cudaGetSymbolAddress(&p_state,  g_state);
    cudaGetSymbolAddress(&p_ticket, g_ticket);
    cudaMemsetAsync(p_cursor, 0, NN * sizeof(int));
    cudaMemsetAsync(p_state,  0, SCAN_G * sizeof(unsigned long long));
    cudaMemsetAsync(p_ticket, 0, sizeof(int));

    k_hist<<<(NE + 255) / 256, 256>>>(ei);
    k_scan<<<SCAN_G, 512>>>();
    k_fill<<<(NE + 255) / 256, 256>>>(ei);

    cudaFuncSetAttribute(precompute_kernel,
                         cudaFuncAttributeMaxDynamicSharedMemorySize,
                         PC_SMEM * sizeof(float));
    precompute_kernel<<<(NN + 127) / 128, 256, PC_SMEM * sizeof(float)>>>(
        x, W1l, W1r, b1);

    gather_l1_proj_kernel<<<(NN + 15) / 16, 256, GH_SMEM * sizeof(float)>>>(
        W2l, W2r, b2);

    final_kernel<<<(NN + 63) / 64, 256>>>(out);
}

// round 7
// speedup vs baseline: 1.3148x; 1.3148x over previous
#include <cuda_runtime.h>
#include <math.h>

#define NN 100000
#define NE 1600000
#define SCAN_G 196   // ceil(100000/512)

// ---------------- scratch (__device__ globals; no allocation) ----------------
__device__ __align__(16) int   g_rowptr[NN + 1];
__device__ __align__(16) int   g_cursor[NN];
__device__ __align__(16) int   g_csr[NE];
__device__ __align__(16) float g_mean[NN * 64];   // mean of x over in-neighbors
__device__ __align__(16) float g_pq[NN * 32];     // per node: [p2(16) | q2(16)]
__device__ unsigned long long  g_state[SCAN_G];
__device__ int                 g_ticket;

// ---------------- packed f32x2 helpers ----------------
__device__ __forceinline__ unsigned long long bcast2(float a) {
    unsigned long long r;
    asm("mov.b64 %0,{%1,%1};" : "=l"(r) : "f"(a));
    return r;
}
__device__ __forceinline__ float2 unpk2(unsigned long long v) {
    float2 r;
    asm("mov.b64 {%0,%1},%2;" : "=f"(r.x), "=f"(r.y) : "l"(v));
    return r;
}
#define FMA2(d, a, b, c) asm("fma.rn.f32x2 %0,%1,%2,%3;" : "=l"(d) : "l"(a), "l"(b), "l"(c))
#define ADD2(d, a, b)    asm("add.rn.f32x2 %0,%1,%2;"    : "=l"(d) : "l"(a), "l"(b))
#define MUL2(d, a, b)    asm("mul.rn.f32x2 %0,%1,%2;"    : "=l"(d) : "l"(a), "l"(b))

// ---------------------------------------------------------------------------
// CSR build
// ---------------------------------------------------------------------------
__global__ void k_hist(const int* __restrict__ ei) {
    int e = blockIdx.x * blockDim.x + threadIdx.x;
    if (e < NE) atomicAdd(&g_cursor[__ldg(ei + NE + e)], 1);
}

__device__ __forceinline__ int warp_incl_scan(int v) {
    int lane = threadIdx.x & 31;
#pragma unroll
    for (int d = 1; d < 32; d <<= 1) {
        int t = __shfl_up_sync(0xFFFFFFFFu, v, d);
        if (lane >= d) v += t;
    }
    return v;
}

__global__ void __launch_bounds__(512) k_scan() {
    __shared__ int ws[16];
    __shared__ int sbid;
    __shared__ int s_prefix;
    int tid = threadIdx.x;
    if (tid == 0) { sbid = atomicAdd(&g_ticket, 1); s_prefix = 0; }
    __syncthreads();
    int bid = sbid;
    int g = bid * 512 + tid;
    int v = (g < NN) ? g_cursor[g] : 0;
    int inc = warp_incl_scan(v);
    int wid = tid >> 5, lane = tid & 31;
    if (lane == 31) ws[wid] = inc;
    __syncthreads();
    if (wid == 0) {
        int t = (lane < 16) ? ws[lane] : 0;
        t = warp_incl_scan(t);
        if (lane < 16) ws[lane] = t;
    }
    __syncthreads();
    int off = (wid > 0) ? ws[wid - 1] : 0;
    int linc = inc + off;

    if (tid == 511) {
        unsigned long long pk = ((unsigned long long)linc << 2) | (bid == 0 ? 2ull : 1ull);
        __threadfence();
        atomicExch(&g_state[bid], pk);
    }
    if (bid > 0 && tid == 0) {
        long long run = 0;
        int p = bid - 1;
        while (true) {
            unsigned long long st;
            do { st = *((volatile unsigned long long*)&g_state[p]); } while ((st & 3ull) == 0);
            run += (long long)(st >> 2);
            if ((st & 3ull) == 2ull) break;
            p--;
        }
        s_prefix = (int)run;
    }
    __syncthreads();
    int pref = s_prefix;
    if (bid > 0 && tid == 511) {
        unsigned long long pk = ((unsigned long long)(pref + linc) << 2) | 2ull;
        __threadfence();
        atomicExch(&g_state[bid], pk);
    }
    int excl = pref + (linc - v);
    if (g < NN) { g_rowptr[g] = excl; g_cursor[g] = excl; }
    if (g == NN) g_rowptr[NN] = excl;
}

__global__ void k_fill(const int* __restrict__ ei) {
    int e = blockIdx.x * blockDim.x + threadIdx.x;
    if (e < NE) {
        int src = __ldg(ei + e);
        int dst = __ldg(ei + NE + e);
        int pos = atomicAdd(&g_cursor[dst], 1);
        g_csr[pos] = src;
    }
}

// ---------------------------------------------------------------------------
// Gather 1: g_mean[n] = mean of x[src]. 16 lanes/node, LDG.128/lane, unroll x4.
// ---------------------------------------------------------------------------
__global__ void __launch_bounds__(256) gather1_kernel(const float* __restrict__ x) {
    int node = blockIdx.x * 16 + (threadIdx.x >> 4);
    int c = threadIdx.x & 15;
    if (node >= NN) return;
    int s = __ldg(g_rowptr + node);
    int e = __ldg(g_rowptr + node + 1);
    unsigned long long a0 = 0ull, a1 = 0ull;
    const ulonglong2* x2 = (const ulonglong2*)x;
    int i = s;
    for (; i + 4 <= e; i += 4) {
        int s0 = __ldg(g_csr + i);
        int s1 = __ldg(g_csr + i + 1);
        int s2 = __ldg(g_csr + i + 2);
        int s3 = __ldg(g_csr + i + 3);
        ulonglong2 v0 = __ldg(x2 + (size_t)s0 * 16 + c);
        ulonglong2 v1 = __ldg(x2 + (size_t)s1 * 16 + c);
        ulonglong2 v2 = __ldg(x2 + (size_t)s2 * 16 + c);
        ulonglong2 v3 = __ldg(x2 + (size_t)s3 * 16 + c);
        ADD2(a0, a0, v0.x); ADD2(a1, a1, v0.y);
        ADD2(a0, a0, v1.x); ADD2(a1, a1, v1.y);
        ADD2(a0, a0, v2.x); ADD2(a1, a1, v2.y);
        ADD2(a0, a0, v3.x); ADD2(a1, a1, v3.y);
    }
    for (; i < e; i++) {
        int s0 = __ldg(g_csr + i);
        ulonglong2 v0 = __ldg(x2 + (size_t)s0 * 16 + c);
        ADD2(a0, a0, v0.x); ADD2(a1, a1, v0.y);
    }
    unsigned long long I = bcast2(1.f / fmaxf((float)(e - s), 1.f));
    ulonglong2 o;
    MUL2(o.x, a0, I);
    MUL2(o.y, a1, I);
    ((ulonglong2*)g_mean)[(size_t)node * 16 + c] = o;
}

// ---------------------------------------------------------------------------
// Dense: 128 threads, 128 nodes/block. Thread = 2 nodes x 32 cols (col half).
// Phase A: h1 = relu(mean@W1l + x@W1r + b1) -> registers.
// Phase B: partial [p2|q2] over own 32 k's, then shfl_xor(1) pair-reduce.
// FMA2:LDS ratio ~3.2:1 (A), 4:1 (B) -- smem crossbar no longer binding.
// ---------------------------------------------------------------------------
#define TSD 129
#define DSM_FLOATS (4096 + 4096 + 2048 + 2 * 16 * TSD + 32 + 64)

__global__ void __launch_bounds__(128) dense_kernel(
    const float* __restrict__ x,
    const float* __restrict__ W1l, const float* __restrict__ W1r,
    const float* __restrict__ b1,
    const float* __restrict__ W2l, const float* __restrict__ W2r,
    const float* __restrict__ b2)
{
    extern __shared__ float smem[];
    float* sWl = smem;                 // [k*64 + j]
    float* sWr = sWl + 4096;
    float* sW2 = sWr + 4096;           // [k*32 + j]
    float* sA  = sW2 + 2048;           // [k*TSD + node_local], 16 k
    float* sX  = sA + 16 * TSD;
    float* sB2 = sX + 16 * TSD;        // 32
    float* sB1 = sB2 + 32;             // 64

    int tid = threadIdx.x;
    int nbase = blockIdx.x * 128;

    for (int i = tid; i < 1024; i += 128) {
        ((float4*)sWl)[i] = ((const float4*)W1l)[i];
        ((float4*)sWr)[i] = ((const float4*)W1r)[i];
    }
    for (int i = tid; i < 1024; i += 128) {
        int k = i >> 4, j = i & 15;
        sW2[k * 32 + j]      = W2l[i];
        sW2[k * 32 + 16 + j] = W2r[i];
    }
    if (tid < 16) { sB2[tid] = 0.f; sB2[16 + tid] = b2[tid]; }
    if (tid < 64) sB1[tid] = b1[tid];

    int cs = tid & 1;           // column half: cols [cs*32, cs*32+32)
    int np = tid >> 1;          // node pair 0..63
    int nl0 = np * 2, nl1 = nl0 + 1;
    int jb = cs * 32;

    // accA[0..15]: node0 colpairs, accA[16..31]: node1 colpairs
    unsigned long long accA[32];
#pragma unroll
    for (int j = 0; j < 32; j++) accA[j] = 0ull;

    const float4* x4 = (const float4*)x;
    const float4* m4 = (const float4*)g_mean;
    float4 z4 = make_float4(0.f, 0.f, 0.f, 0.f);

    for (int kb = 0; kb < 4; kb++) {
        __syncthreads();
        for (int i = tid; i < 512; i += 128) {
            int nn = i >> 2, cc = i & 3;
            int gn = nbase + nn;
            float4 va = (gn < NN) ? __ldg(m4 + (size_t)gn * 16 + kb * 4 + cc) : z4;
            float4 vx = (gn < NN) ? __ldg(x4 + (size_t)gn * 16 + kb * 4 + cc) : z4;
            int kr = cc * 4;
            sA[(kr + 0) * TSD + nn] = va.x;
            sA[(kr + 1) * TSD + nn] = va.y;
            sA[(kr + 2) * TSD + nn] = va.z;
            sA[(kr + 3) * TSD + nn] = va.w;
            sX[(kr + 0) * TSD + nn] = vx.x;
            sX[(kr + 1) * TSD + nn] = vx.y;
            sX[(kr + 2) * TSD + nn] = vx.z;
            sX[(kr + 3) * TSD + nn] = vx.w;
        }
        __syncthreads();
#pragma unroll
        for (int k = 0; k < 16; k++) {
            int kg = kb * 16 + k;
            unsigned long long A0 = bcast2(sA[k * TSD + nl0]);
            unsigned long long A1 = bcast2(sA[k * TSD + nl1]);
            unsigned long long X0 = bcast2(sX[k * TSD + nl0]);
            unsigned long long X1 = bcast2(sX[k * TSD + nl1]);
            const ulonglong2* wl = (const ulonglong2*)(sWl + kg * 64 + jb);
            const ulonglong2* wr = (const ulonglong2*)(sWr + kg * 64 + jb);
#pragma unroll
            for (int jh = 0; jh < 8; jh++) {
                ulonglong2 wwl = wl[jh];
                ulonglong2 wwr = wr[jh];
                FMA2(accA[2 * jh],          A0, wwl.x, accA[2 * jh]);
                FMA2(accA[2 * jh + 1],      A0, wwl.y, accA[2 * jh + 1]);
                FMA2(accA[16 + 2 * jh],     A1, wwl.x, accA[16 + 2 * jh]);
                FMA2(accA[16 + 2 * jh + 1], A1, wwl.y, accA[16 + 2 * jh + 1]);
                FMA2(accA[2 * jh],          X0, wwr.x, accA[2 * jh]);
                FMA2(accA[2 * jh + 1],      X0, wwr.y, accA[2 * jh + 1]);
                FMA2(accA[16 + 2 * jh],     X1, wwr.x, accA[16 + 2 * jh]);
                FMA2(accA[16 + 2 * jh + 1], X1, wwr.y, accA[16 + 2 * jh + 1]);
            }
        }
    }

    // h1 for 2 nodes x this col half, in registers
    float h1s[2][32];
#pragma unroll
    for (int p = 0; p < 16; p++) {
        float b0 = sB1[jb + 2 * p];
        float b1v = sB1[jb + 2 * p + 1];
        float2 u0 = unpk2(accA[p]);
        float2 u1 = unpk2(accA[16 + p]);
        h1s[0][2 * p]     = fmaxf(u0.x + b0,  0.f);
        h1s[0][2 * p + 1] = fmaxf(u0.y + b1v, 0.f);
        h1s[1][2 * p]     = fmaxf(u1.x + b0,  0.f);
        h1s[1][2 * p + 1] = fmaxf(u1.y + b1v, 0.f);
    }

    // Phase B: partial products over k = jb..jb+31
    unsigned long long accB[32];
#pragma unroll
    for (int j = 0; j < 32; j++) accB[j] = 0ull;
#pragma unroll
    for (int kk = 0; kk < 32; kk++) {
        int k = jb + kk;
        const ulonglong2* w2 = (const ulonglong2*)(sW2 + k * 32);
        unsigned long long H0 = bcast2(h1s[0][kk]);
        unsigned long long H1 = bcast2(h1s[1][kk]);
#pragma unroll
        for (int jh = 0; jh < 8; jh++) {
            ulonglong2 w = w2[jh];
            FMA2(accB[2 * jh],          H0, w.x, accB[2 * jh]);
            FMA2(accB[2 * jh + 1],      H0, w.y, accB[2 * jh + 1]);
            FMA2(accB[16 + 2 * jh],     H1, w.x, accB[16 + 2 * jh]);
            FMA2(accB[16 + 2 * jh + 1], H1, w.y, accB[16 + 2 * jh + 1]);
        }
    }
    // pair-reduce the two col-halves (lanes 2i <-> 2i+1)
#pragma unroll
    for (int j = 0; j < 32; j++) {
        unsigned long long o = __shfl_xor_sync(0xFFFFFFFFu, accB[j], 1);
        ADD2(accB[j], accB[j], o);
    }
    // cs==0 writes node nl0 (accB[0..15]), cs==1 writes node nl1 (accB[16..31])
    int node = nbase + (cs ? nl1 : nl0);
    const unsigned long long* mine = accB + cs * 16;
    if (node < NN) {
        float o[32];
#pragma unroll
        for (int p = 0; p < 16; p++) {
            float2 u = unpk2(mine[p]);
            o[2 * p]     = u.x + sB2[2 * p];
            o[2 * p + 1] = u.y + sB2[2 * p + 1];
        }
        float4* dst = (float4*)(g_pq + (size_t)node * 32);
#pragma unroll
        for (int q = 0; q < 8; q++) dst[q] = *(float4*)(o + 4 * q);
    }
}

// ---------------------------------------------------------------------------
// Final: gather mean(p2) + q2 -> log_softmax -> out. 4 lanes/node, unroll x4.
// ---------------------------------------------------------------------------
__global__ void __launch_bounds__(256) final_kernel(float* __restrict__ out) {
    int tid = threadIdx.x;
    int node = blockIdx.x * 64 + (tid >> 2);
    int c = tid & 3;
    bool nv = node < NN;
    int s = 0, e = 0;
    if (nv) { s = __ldg(g_rowptr + node); e = __ldg(g_rowptr + node + 1); }
    unsigned long long a0 = 0ull, a1 = 0ull;
    const ulonglong2* pq2 = (const ulonglong2*)g_pq;
    int i = s;
    for (; i + 4 <= e; i += 4) {
        int s0 = __ldg(g_csr + i);
        int s1 = __ldg(g_csr + i + 1);
        int s2 = __ldg(g_csr + i + 2);
        int s3 = __ldg(g_csr + i + 3);
        ulonglong2 v0 = __ldg(pq2 + (size_t)s0 * 8 + c);
        ulonglong2 v1 = __ldg(pq2 + (size_t)s1 * 8 + c);
        ulonglong2 v2 = __ldg(pq2 + (size_t)s2 * 8 + c);
        ulonglong2 v3 = __ldg(pq2 + (size_t)s3 * 8 + c);
        ADD2(a0, a0, v0.x); ADD2(a1, a1, v0.y);
        ADD2(a0, a0, v1.x); ADD2(a1, a1, v1.y);
        ADD2(a0, a0, v2.x); ADD2(a1, a1, v2.y);
        ADD2(a0, a0, v3.x); ADD2(a1, a1, v3.y);
    }
    for (; i < e; i++) {
        int s0 = __ldg(g_csr + i);
        ulonglong2 v0 = __ldg(pq2 + (size_t)s0 * 8 + c);
        ADD2(a0, a0, v0.x); ADD2(a1, a1, v0.y);
    }
    float invd = 1.f / fmaxf((float)(e - s), 1.f);
    float2 u0 = unpk2(a0), u1 = unpk2(a1);
    float4 q = nv ? __ldg((const float4*)g_pq + (size_t)node * 8 + 4 + c)
                  : make_float4(0.f, 0.f, 0.f, 0.f);
    float v[4];
    v[0] = u0.x * invd + q.x;
    v[1] = u0.y * invd + q.y;
    v[2] = u1.x * invd + q.z;
    v[3] = u1.y * invd + q.w;

    float m = fmaxf(fmaxf(v[0], v[1]), fmaxf(v[2], v[3]));
    m = fmaxf(m, __shfl_xor_sync(0xFFFFFFFFu, m, 1));
    m = fmaxf(m, __shfl_xor_sync(0xFFFFFFFFu, m, 2));
    float sum = expf(v[0] - m) + expf(v[1] - m) + expf(v[2] - m) + expf(v[3] - m);
    sum += __shfl_xor_sync(0xFFFFFFFFu, sum, 1);
    sum += __shfl_xor_sync(0xFFFFFFFFu, sum, 2);
    float lse = m + logf(sum);

    if (nv) {
        float4 o;
        o.x = v[0] - lse; o.y = v[1] - lse; o.z = v[2] - lse; o.w = v[3] - lse;
        ((float4*)out)[(size_t)node * 4 + c] = o;
    }
}

// ---------------------------------------------------------------------------
extern "C" void kernel_launch(void* const* d_in, const int* in_sizes, int n_in,
                              void* d_out, int out_size) {
    const float* x   = (const float*)d_in[0];
    const int*   ei  = (const int*)d_in[1];
    const float* W1l = (const float*)d_in[2];
    const float* W1r = (const float*)d_in[3];
    const float* b1  = (const float*)d_in[4];
    const float* W2l = (const float*)d_in[5];
    const float* W2r = (const float*)d_in[6];
    const float* b2  = (const float*)d_in[7];
    float* out = (float*)d_out;

    void *p_cursor, *p_state, *p_ticket;
    cudaGetSymbolAddress(&p_cursor, g_cursor);
    cudaGetSymbolAddress(&p_state,  g_state);
    cudaGetSymbolAddress(&p_ticket, g_ticket);
    cudaMemsetAsync(p_cursor, 0, NN * sizeof(int));
    cudaMemsetAsync(p_state,  0, SCAN_G * sizeof(unsigned long long));
    cudaMemsetAsync(p_ticket, 0, sizeof(int));

    k_hist<<<(NE + 255) / 256, 256>>>(ei);
    k_scan<<<SCAN_G, 512>>>();
    k_fill<<<(NE + 255) / 256, 256>>>(ei);

    gather1_kernel<<<(NN + 15) / 16, 256>>>(x);

    cudaFuncSetAttribute(dense_kernel,
                         cudaFuncAttributeMaxDynamicSharedMemorySize,
                         DSM_FLOATS * sizeof(float));
    dense_kernel<<<(NN + 127) / 128, 128, DSM_FLOATS * sizeof(float)>>>(
        x, W1l, W1r, b1, W2l, W2r, b2);

    final_kernel<<<(NN + 63) / 64, 256>>>(out);
}

// round 8
// speedup vs baseline: 1.3532x; 1.0292x over previous
#include <cuda_runtime.h>
#include <math.h>

#define NN 100000
#define NE 1600000
#define SCAN_G 196   // ceil(100000/512)

// ---------------- scratch (__device__ globals; no allocation) ----------------
__device__ __align__(16) int   g_rowptr[NN + 1];
__device__ __align__(16) int   g_cursor[NN];
__device__ __align__(16) int   g_csr[NE];
__device__ __align__(16) float g_mean[NN * 64];   // mean of x over in-neighbors
__device__ __align__(16) float g_pq[NN * 32];     // per node: [p2(16) | q2(16)]
__device__ unsigned long long  g_state[SCAN_G];
__device__ int                 g_ticket;

// ---------------- packed f32x2 helpers ----------------
__device__ __forceinline__ unsigned long long bcast2(float a) {
    unsigned long long r;
    asm("mov.b64 %0,{%1,%1};" : "=l"(r) : "f"(a));
    return r;
}
__device__ __forceinline__ float2 unpk2(unsigned long long v) {
    float2 r;
    asm("mov.b64 {%0,%1},%2;" : "=f"(r.x), "=f"(r.y) : "l"(v));
    return r;
}
#define FMA2(d, a, b, c) asm("fma.rn.f32x2 %0,%1,%2,%3;" : "=l"(d) : "l"(a), "l"(b), "l"(c))
#define ADD2(d, a, b)    asm("add.rn.f32x2 %0,%1,%2;"    : "=l"(d) : "l"(a), "l"(b))
#define MUL2(d, a, b)    asm("mul.rn.f32x2 %0,%1,%2;"    : "=l"(d) : "l"(a), "l"(b))

// ---------------------------------------------------------------------------
// Zero all accumulated state in ONE launch (keeps ncu -s 5 aimed at dense).
// ---------------------------------------------------------------------------
__global__ void k_zero() {
    int g = blockIdx.x * blockDim.x + threadIdx.x;
    int stride = gridDim.x * blockDim.x;
    for (int t = g; t < NN; t += stride) g_cursor[t] = 0;
    if (g < SCAN_G) g_state[g] = 0ull;
    if (g == 0) g_ticket = 0;
}

// ---------------------------------------------------------------------------
// CSR build
// ---------------------------------------------------------------------------
__global__ void k_hist(const int* __restrict__ ei) {
    int e = blockIdx.x * blockDim.x + threadIdx.x;
    if (e < NE) atomicAdd(&g_cursor[__ldg(ei + NE + e)], 1);
}

__device__ __forceinline__ int warp_incl_scan(int v) {
    int lane = threadIdx.x & 31;
#pragma unroll
    for (int d = 1; d < 32; d <<= 1) {
        int t = __shfl_up_sync(0xFFFFFFFFu, v, d);
        if (lane >= d) v += t;
    }
    return v;
}

__global__ void __launch_bounds__(512) k_scan() {
    __shared__ int ws[16];
    __shared__ int sbid;
    __shared__ int s_prefix;
    int tid = threadIdx.x;
    if (tid == 0) { sbid = atomicAdd(&g_ticket, 1); s_prefix = 0; }
    __syncthreads();
    int bid = sbid;
    int g = bid * 512 + tid;
    int v = (g < NN) ? g_cursor[g] : 0;
    int inc = warp_incl_scan(v);
    int wid = tid >> 5, lane = tid & 31;
    if (lane == 31) ws[wid] = inc;
    __syncthreads();
    if (wid == 0) {
        int t = (lane < 16) ? ws[lane] : 0;
        t = warp_incl_scan(t);
        if (lane < 16) ws[lane] = t;
    }
    __syncthreads();
    int off = (wid > 0) ? ws[wid - 1] : 0;
    int linc = inc + off;

    if (tid == 511) {
        unsigned long long pk = ((unsigned long long)linc << 2) | (bid == 0 ? 2ull : 1ull);
        __threadfence();
        atomicExch(&g_state[bid], pk);
    }
    if (bid > 0 && tid == 0) {
        long long run = 0;
        int p = bid - 1;
        while (true) {
            unsigned long long st;
            do { st = *((volatile unsigned long long*)&g_state[p]); } while ((st & 3ull) == 0);
            run += (long long)(st >> 2);
            if ((st & 3ull) == 2ull) break;
            p--;
        }
        s_prefix = (int)run;
    }
    __syncthreads();
    int pref = s_prefix;
    if (bid > 0 && tid == 511) {
        unsigned long long pk = ((unsigned long long)(pref + linc) << 2) | 2ull;
        __threadfence();
        atomicExch(&g_state[bid], pk);
    }
    int excl = pref + (linc - v);
    if (g < NN) { g_rowptr[g] = excl; g_cursor[g] = excl; }
    if (g == NN) g_rowptr[NN] = excl;
}

__global__ void k_fill(const int* __restrict__ ei) {
    int e = blockIdx.x * blockDim.x + threadIdx.x;
    if (e < NE) {
        int src = __ldg(ei + e);
        int dst = __ldg(ei + NE + e);
        int pos = atomicAdd(&g_cursor[dst], 1);
        g_csr[pos] = src;
    }
}

// ---------------------------------------------------------------------------
// Gather 1: g_mean[n] = mean of x[src]. 16 lanes/node, LDG.128/lane, unroll x4.
// At the LTS ceiling (~12.4TB/s) -- do not touch.
// ---------------------------------------------------------------------------
__global__ void __launch_bounds__(256) gather1_kernel(const float* __restrict__ x) {
    int node = blockIdx.x * 16 + (threadIdx.x >> 4);
    int c = threadIdx.x & 15;
    if (node >= NN) return;
    int s = __ldg(g_rowptr + node);
    int e = __ldg(g_rowptr + node + 1);
    unsigned long long a0 = 0ull, a1 = 0ull;
    const ulonglong2* x2 = (const ulonglong2*)x;
    int i = s;
    for (; i + 4 <= e; i += 4) {
        int s0 = __ldg(g_csr + i);
        int s1 = __ldg(g_csr + i + 1);
        int s2 = __ldg(g_csr + i + 2);
        int s3 = __ldg(g_csr + i + 3);
        ulonglong2 v0 = __ldg(x2 + (size_t)s0 * 16 + c);
        ulonglong2 v1 = __ldg(x2 + (size_t)s1 * 16 + c);
        ulonglong2 v2 = __ldg(x2 + (size_t)s2 * 16 + c);
        ulonglong2 v3 = __ldg(x2 + (size_t)s3 * 16 + c);
        ADD2(a0, a0, v0.x); ADD2(a1, a1, v0.y);
        ADD2(a0, a0, v1.x); ADD2(a1, a1, v1.y);
        ADD2(a0, a0, v2.x); ADD2(a1, a1, v2.y);
        ADD2(a0, a0, v3.x); ADD2(a1, a1, v3.y);
    }
    for (; i < e; i++) {
        int s0 = __ldg(g_csr + i);
        ulonglong2 v0 = __ldg(x2 + (size_t)s0 * 16 + c);
        ADD2(a0, a0, v0.x); ADD2(a1, a1, v0.y);
    }
    unsigned long long I = bcast2(1.f / fmaxf((float)(e - s), 1.f));
    ulonglong2 o;
    MUL2(o.x, a0, I);
    MUL2(o.y, a1, I);
    ((ulonglong2*)g_mean)[(size_t)node * 16 + c] = o;
}

// ---------------------------------------------------------------------------
// Dense: 128 threads, 128 nodes/block. Thread = 2 nodes x 32 cols (col half).
// ---------------------------------------------------------------------------
#define TSD 129
#define DSM_FLOATS (4096 + 4096 + 2048 + 2 * 16 * TSD + 32 + 64)

__global__ void __launch_bounds__(128) dense_kernel(
    const float* __restrict__ x,
    const float* __restrict__ W1l, const float* __restrict__ W1r,
    const float* __restrict__ b1,
    const float* __restrict__ W2l, const float* __restrict__ W2r,
    const float* __restrict__ b2)
{
    extern __shared__ float smem[];
    float* sWl = smem;                 // [k*64 + j]
    float* sWr = sWl + 4096;
    float* sW2 = sWr + 4096;           // [k*32 + j]
    float* sA  = sW2 + 2048;           // [k*TSD + node_local], 16 k
    float* sX  = sA + 16 * TSD;
    float* sB2 = sX + 16 * TSD;        // 32
    float* sB1 = sB2 + 32;             // 64

    int tid = threadIdx.x;
    int nbase = blockIdx.x * 128;

    for (int i = tid; i < 1024; i += 128) {
        ((float4*)sWl)[i] = ((const float4*)W1l)[i];
        ((float4*)sWr)[i] = ((const float4*)W1r)[i];
    }
    for (int i = tid; i < 1024; i += 128) {
        int k = i >> 4, j = i & 15;
        sW2[k * 32 + j]      = W2l[i];
        sW2[k * 32 + 16 + j] = W2r[i];
    }
    if (tid < 16) { sB2[tid] = 0.f; sB2[16 + tid] = b2[tid]; }
    if (tid < 64) sB1[tid] = b1[tid];

    int cs = tid & 1;
    int np = tid >> 1;
    int nl0 = np * 2, nl1 = nl0 + 1;
    int jb = cs * 32;

    unsigned long long accA[32];
#pragma unroll
    for (int j = 0; j < 32; j++) accA[j] = 0ull;

    const float4* x4 = (const float4*)x;
    const float4* m4 = (const float4*)g_mean;
    float4 z4 = make_float4(0.f, 0.f, 0.f, 0.f);

    for (int kb = 0; kb < 4; kb++) {
        __syncthreads();
        for (int i = tid; i < 512; i += 128) {
            int nn = i >> 2, cc = i & 3;
            int gn = nbase + nn;
            float4 va = (gn < NN) ? __ldg(m4 + (size_t)gn * 16 + kb * 4 + cc) : z4;
            float4 vx = (gn < NN) ? __ldg(x4 + (size_t)gn * 16 + kb * 4 + cc) : z4;
            int kr = cc * 4;
            sA[(kr + 0) * TSD + nn] = va.x;
            sA[(kr + 1) * TSD + nn] = va.y;
            sA[(kr + 2) * TSD + nn] = va.z;
            sA[(kr + 3) * TSD + nn] = va.w;
            sX[(kr + 0) * TSD + nn] = vx.x;
            sX[(kr + 1) * TSD + nn] = vx.y;
            sX[(kr + 2) * TSD + nn] = vx.z;
            sX[(kr + 3) * TSD + nn] = vx.w;
        }
        __syncthreads();
#pragma unroll
        for (int k = 0; k < 16; k++) {
            int kg = kb * 16 + k;
            unsigned long long A0 = bcast2(sA[k * TSD + nl0]);
            unsigned long long A1 = bcast2(sA[k * TSD + nl1]);
            unsigned long long X0 = bcast2(sX[k * TSD + nl0]);
            unsigned long long X1 = bcast2(sX[k * TSD + nl1]);
            const ulonglong2* wl = (const ulonglong2*)(sWl + kg * 64 + jb);
            const ulonglong2* wr = (const ulonglong2*)(sWr + kg * 64 + jb);
#pragma unroll
            for (int jh = 0; jh < 8; jh++) {
                ulonglong2 wwl = wl[jh];
                ulonglong2 wwr = wr[jh];
                FMA2(accA[2 * jh],          A0, wwl.x, accA[2 * jh]);
                FMA2(accA[2 * jh + 1],      A0, wwl.y, accA[2 * jh + 1]);
                FMA2(accA[16 + 2 * jh],     A1, wwl.x, accA[16 + 2 * jh]);
                FMA2(accA[16 + 2 * jh + 1], A1, wwl.y, accA[16 + 2 * jh + 1]);
                FMA2(accA[2 * jh],          X0, wwr.x, accA[2 * jh]);
                FMA2(accA[2 * jh + 1],      X0, wwr.y, accA[2 * jh + 1]);
                FMA2(accA[16 + 2 * jh],     X1, wwr.x, accA[16 + 2 * jh]);
                FMA2(accA[16 + 2 * jh + 1], X1, wwr.y, accA[16 + 2 * jh + 1]);
            }
        }
    }

    float h1s[2][32];
#pragma unroll
    for (int p = 0; p < 16; p++) {
        float b0 = sB1[jb + 2 * p];
        float b1v = sB1[jb + 2 * p + 1];
        float2 u0 = unpk2(accA[p]);
        float2 u1 = unpk2(accA[16 + p]);
        h1s[0][2 * p]     = fmaxf(u0.x + b0,  0.f);
        h1s[0][2 * p + 1] = fmaxf(u0.y + b1v, 0.f);
        h1s[1][2 * p]     = fmaxf(u1.x + b0,  0.f);
        h1s[1][2 * p + 1] = fmaxf(u1.y + b1v, 0.f);
    }

    unsigned long long accB[32];
#pragma unroll
    for (int j = 0; j < 32; j++) accB[j] = 0ull;
#pragma unroll
    for (int kk = 0; kk < 32; kk++) {
        int k = jb + kk;
        const ulonglong2* w2 = (const ulonglong2*)(sW2 + k * 32);
        unsigned long long H0 = bcast2(h1s[0][kk]);
        unsigned long long H1 = bcast2(h1s[1][kk]);
#pragma unroll
        for (int jh = 0; jh < 8; jh++) {
            ulonglong2 w = w2[jh];
            FMA2(accB[2 * jh],          H0, w.x, accB[2 * jh]);
            FMA2(accB[2 * jh + 1],      H0, w.y, accB[2 * jh + 1]);
            FMA2(accB[16 + 2 * jh],     H1, w.x, accB[16 + 2 * jh]);
            FMA2(accB[16 + 2 * jh + 1], H1, w.y, accB[16 + 2 * jh + 1]);
        }
    }
#pragma unroll
    for (int j = 0; j < 32; j++) {
        unsigned long long o = __shfl_xor_sync(0xFFFFFFFFu, accB[j], 1);
        ADD2(accB[j], accB[j], o);
    }
    int node = nbase + (cs ? nl1 : nl0);
    const unsigned long long* mine = accB + cs * 16;
    if (node < NN) {
        float o[32];
#pragma unroll
        for (int p = 0; p < 16; p++) {
            float2 u = unpk2(mine[p]);
            o[2 * p]     = u.x + sB2[2 * p];
            o[2 * p + 1] = u.y + sB2[2 * p + 1];
        }
        float4* dst = (float4*)(g_pq + (size_t)node * 32);
#pragma unroll
        for (int q = 0; q < 8; q++) dst[q] = *(float4*)(o + 4 * q);
    }
}

// ---------------------------------------------------------------------------
// Final: gather mean(p2) + q2 -> log_softmax -> out. 4 lanes/node, unroll x4.
// ---------------------------------------------------------------------------
__global__ void __launch_bounds__(256) final_kernel(float* __restrict__ out) {
    int tid = threadIdx.x;
    int node = blockIdx.x * 64 + (tid >> 2);
    int c = tid & 3;
    bool nv = node < NN;
    int s = 0, e = 0;
    if (nv) { s = __ldg(g_rowptr + node); e = __ldg(g_rowptr + node + 1); }
    unsigned long long a0 = 0ull, a1 = 0ull;
    const ulonglong2* pq2 = (const ulonglong2*)g_pq;
    int i = s;
    for (; i + 4 <= e; i += 4) {
        int s0 = __ldg(g_csr + i);
        int s1 = __ldg(g_csr + i + 1);
        int s2 = __ldg(g_csr + i + 2);
        int s3 = __ldg(g_csr + i + 3);
        ulonglong2 v0 = __ldg(pq2 + (size_t)s0 * 8 + c);
        ulonglong2 v1 = __ldg(pq2 + (size_t)s1 * 8 + c);
        ulonglong2 v2 = __ldg(pq2 + (size_t)s2 * 8 + c);
        ulonglong2 v3 = __ldg(pq2 + (size_t)s3 * 8 + c);
        ADD2(a0, a0, v0.x); ADD2(a1, a1, v0.y);
        ADD2(a0, a0, v1.x); ADD2(a1, a1, v1.y);
        ADD2(a0, a0, v2.x); ADD2(a1, a1, v2.y);
        ADD2(a0, a0, v3.x); ADD2(a1, a1, v3.y);
    }
    for (; i < e; i++) {
        int s0 = __ldg(g_csr + i);
        ulonglong2 v0 = __ldg(pq2 + (size_t)s0 * 8 + c);
        ADD2(a0, a0, v0.x); ADD2(a1, a1, v0.y);
    }
    float invd = 1.f / fmaxf((float)(e - s), 1.f);
    float2 u0 = unpk2(a0), u1 = unpk2(a1);
    float4 q = nv ? __ldg((const float4*)g_pq + (size_t)node * 8 + 4 + c)
                  : make_float4(0.f, 0.f, 0.f, 0.f);
    float v[4];
    v[0] = u0.x * invd + q.x;
    v[1] = u0.y * invd + q.y;
    v[2] = u1.x * invd + q.z;
    v[3] = u1.y * invd + q.w;

    float m = fmaxf(fmaxf(v[0], v[1]), fmaxf(v[2], v[3]));
    m = fmaxf(m, __shfl_xor_sync(0xFFFFFFFFu, m, 1));
    m = fmaxf(m, __shfl_xor_sync(0xFFFFFFFFu, m, 2));
    float sum = expf(v[0] - m) + expf(v[1] - m) + expf(v[2] - m) + expf(v[3] - m);
    sum += __shfl_xor_sync(0xFFFFFFFFu, sum, 1);
    sum += __shfl_xor_sync(0xFFFFFFFFu, sum, 2);
    float lse = m + logf(sum);

    if (nv) {
        float4 o;
        o.x = v[0] - lse; o.y = v[1] - lse; o.z = v[2] - lse; o.w = v[3] - lse;
        ((float4*)out)[(size_t)node * 4 + c] = o;
    }
}

// ---------------------------------------------------------------------------
extern "C" void kernel_launch(void* const* d_in, const int* in_sizes, int n_in,
                              void* d_out, int out_size) {
    const float* x   = (const float*)d_in[0];
    const int*   ei  = (const int*)d_in[1];
    const float* W1l = (const float*)d_in[2];
    const float* W1r = (const float*)d_in[3];
    const float* b1  = (const float*)d_in[4];
    const float* W2l = (const float*)d_in[5];
    const float* W2r = (const float*)d_in[6];
    const float* b2  = (const float*)d_in[7];
    float* out = (float*)d_out;

    k_zero<<<256, 512>>>();                       // launch 0
    k_hist<<<(NE + 255) / 256, 256>>>(ei);        // 1
    k_scan<<<SCAN_G, 512>>>();                    // 2
    k_fill<<<(NE + 255) / 256, 256>>>(ei);        // 3
    gather1_kernel<<<(NN + 15) / 16, 256>>>(x);   // 4

    cudaFuncSetAttribute(dense_kernel,
                         cudaFuncAttributeMaxDynamicSharedMemorySize,
                         DSM_FLOATS * sizeof(float));
    dense_kernel<<<(NN + 127) / 128, 128, DSM_FLOATS * sizeof(float)>>>(
        x, W1l, W1r, b1, W2l, W2r, b2);           // 5  <- ncu -s 5 profiles this

    final_kernel<<<(NN + 63) / 64, 256>>>(out);   // 6
}